// round 1
// baseline (speedup 1.0000x reference)
#include <cuda_runtime.h>
#include <math.h>

#define BATCH  64
#define CDIM   384
#define HIN    28
#define WIN    28
#define LQ     785     // 1 + 28*28
#define LKV    197     // 1 + 14*14
#define NHEADS 6
#define HDIM   64
#define EPSB   1e-5f
#define QSCALE 0.051031036307982884f   // 384^-0.5

// ---------------- device scratch (no allocations allowed) ----------------
__device__ float g_qc[BATCH * LQ  * CDIM];   // conv+BN q  (with cls row 0)
__device__ float g_kc[BATCH * LKV * CDIM];   // conv+BN k
__device__ float g_vc[BATCH * LKV * CDIM];   // conv+BN v
__device__ float g_Q [BATCH * LQ  * CDIM];   // after W_q
__device__ float g_K [BATCH * LKV * CDIM];   // after W_k
__device__ float g_V [BATCH * LKV * CDIM];   // after W_v

// ---------------- cls token copy into conv buffers ----------------
__global__ void cls_copy_kernel(const float* __restrict__ hs) {
    int b = blockIdx.x, c = threadIdx.x;
    float v = hs[(size_t)b * LQ * CDIM + c];
    g_qc[(size_t)b * LQ  * CDIM + c] = v;
    g_kc[(size_t)b * LKV * CDIM + c] = v;
    g_vc[(size_t)b * LKV * CDIM + c] = v;
}

// ---------------- depthwise 3x3 stride-1 conv + BN (q path) ----------------
__global__ __launch_bounds__(CDIM) void conv_q_kernel(
    const float* __restrict__ hs,
    const float* __restrict__ wdw, const float* __restrict__ gam,
    const float* __restrict__ bet, const float* __restrict__ mean,
    const float* __restrict__ var) {
    int c   = threadIdx.x;
    int pos = blockIdx.x % (HIN * WIN);
    int b   = blockIdx.x / (HIN * WIN);
    int oh = pos / WIN, ow = pos % WIN;
    const float* xb = hs + (size_t)b * LQ * CDIM + CDIM;   // skip cls row
    float acc = 0.f;
#pragma unroll
    for (int kh = 0; kh < 3; kh++) {
        int ih = oh + kh - 1;
        if ((unsigned)ih >= HIN) continue;
#pragma unroll
        for (int kw = 0; kw < 3; kw++) {
            int iw = ow + kw - 1;
            if ((unsigned)iw >= WIN) continue;
            acc = fmaf(xb[(ih * WIN + iw) * CDIM + c],
                       wdw[(kh * 3 + kw) * CDIM + c], acc);
        }
    }
    float s = gam[c] * rsqrtf(var[c] + EPSB);
    g_qc[(size_t)b * LQ * CDIM + (size_t)(1 + pos) * CDIM + c] =
        acc * s + (bet[c] - mean[c] * s);
}

// ---------------- depthwise 3x3 stride-2 conv + BN (k and v together) ----------------
__global__ __launch_bounds__(CDIM) void conv_kv_kernel(
    const float* __restrict__ hs,
    const float* __restrict__ wk, const float* __restrict__ gk,
    const float* __restrict__ bek, const float* __restrict__ mk,
    const float* __restrict__ vk,
    const float* __restrict__ wv, const float* __restrict__ gv,
    const float* __restrict__ bev, const float* __restrict__ mv,
    const float* __restrict__ vvv) {
    int c   = threadIdx.x;
    int pos = blockIdx.x % 196;
    int b   = blockIdx.x / 196;
    int oh = pos / 14, ow = pos % 14;
    const float* xb = hs + (size_t)b * LQ * CDIM + CDIM;
    float ak = 0.f, av = 0.f;
#pragma unroll
    for (int kh = 0; kh < 3; kh++) {
        int ih = oh * 2 + kh - 1;
        if ((unsigned)ih >= HIN) continue;
#pragma unroll
        for (int kw = 0; kw < 3; kw++) {
            int iw = ow * 2 + kw - 1;
            if ((unsigned)iw >= WIN) continue;
            float x = xb[(ih * WIN + iw) * CDIM + c];
            ak = fmaf(x, wk[(kh * 3 + kw) * CDIM + c], ak);
            av = fmaf(x, wv[(kh * 3 + kw) * CDIM + c], av);
        }
    }
    float sk = gk[c] * rsqrtf(vk[c]  + EPSB);
    float sv = gv[c] * rsqrtf(vvv[c] + EPSB);
    size_t o = (size_t)b * LKV * CDIM + (size_t)(1 + pos) * CDIM + c;
    g_kc[o] = ak * sk + (bek[c] - mk[c] * sk);
    g_vc[o] = av * sv + (bev[c] - mv[c] * sv);
}

// ---------------- GEMM: C = A(Mx384) @ W(384x384) + bias ----------------
// 64x128 block tile, BK=16, 256 threads, 4x8 micro-tile. M is exact multiple of 64.
template <int SEL>
__global__ __launch_bounds__(256) void gemm_bias_kernel(
    const float* __restrict__ Wt, const float* __restrict__ bias) {
    const float* A;
    float* Co;
    if (SEL == 0)      { A = g_qc; Co = g_Q; }
    else if (SEL == 1) { A = g_kc; Co = g_K; }
    else               { A = g_vc; Co = g_V; }

    __shared__ float As[16][68];    // A tile transposed [k][m], padded
    __shared__ float Bs[16][128];   // W tile [k][n]

    const int tid = threadIdx.x;
    const int bn  = blockIdx.x * 128;
    const size_t bm = (size_t)blockIdx.y * 64;
    const int tx = tid & 15;        // 16 col groups
    const int ty = tid >> 4;        // 16 row groups
    const int arow = tid >> 2;              // 0..63
    const int ak   = (tid & 3) << 2;        // 0,4,8,12
    const int brow = tid >> 5;              // 0..7
    const int bcol = (tid & 31) << 2;       // 0..124

    const float* Ag = A + (bm + arow) * CDIM + ak;
    const float* Bg = Wt + (size_t)brow * CDIM + bn + bcol;

    float acc[4][8];
#pragma unroll
    for (int i = 0; i < 4; i++)
#pragma unroll
        for (int j = 0; j < 8; j++) acc[i][j] = 0.f;

    for (int k0 = 0; k0 < CDIM; k0 += 16) {
        float4 a4 = *(const float4*)(Ag + k0);
        As[ak + 0][arow] = a4.x;
        As[ak + 1][arow] = a4.y;
        As[ak + 2][arow] = a4.z;
        As[ak + 3][arow] = a4.w;
        *(float4*)&Bs[brow][bcol]     = *(const float4*)(Bg + (size_t)k0 * CDIM);
        *(float4*)&Bs[brow + 8][bcol] = *(const float4*)(Bg + (size_t)(k0 + 8) * CDIM);
        __syncthreads();
#pragma unroll
        for (int k = 0; k < 16; k++) {
            float4 av = *(const float4*)&As[k][ty * 4];
            float4 b0 = *(const float4*)&Bs[k][tx * 4];
            float4 b1 = *(const float4*)&Bs[k][64 + tx * 4];
            float a[4]  = {av.x, av.y, av.z, av.w};
            float bb[8] = {b0.x, b0.y, b0.z, b0.w, b1.x, b1.y, b1.z, b1.w};
#pragma unroll
            for (int i = 0; i < 4; i++)
#pragma unroll
                for (int j = 0; j < 8; j++)
                    acc[i][j] = fmaf(a[i], bb[j], acc[i][j]);
        }
        __syncthreads();
    }
#pragma unroll
    for (int i = 0; i < 4; i++) {
        size_t row = bm + (size_t)(ty * 4 + i);
        float* Cp = Co + row * CDIM + bn;
        float4 o0, o1;
        o0.x = acc[i][0] + bias[bn + tx * 4 + 0];
        o0.y = acc[i][1] + bias[bn + tx * 4 + 1];
        o0.z = acc[i][2] + bias[bn + tx * 4 + 2];
        o0.w = acc[i][3] + bias[bn + tx * 4 + 3];
        o1.x = acc[i][4] + bias[bn + 64 + tx * 4 + 0];
        o1.y = acc[i][5] + bias[bn + 64 + tx * 4 + 1];
        o1.z = acc[i][6] + bias[bn + 64 + tx * 4 + 2];
        o1.w = acc[i][7] + bias[bn + 64 + tx * 4 + 3];
        *(float4*)(Cp + tx * 4)      = o0;
        *(float4*)(Cp + 64 + tx * 4) = o1;
    }
}

// ---------------- attention: one CTA per (batch, head) ----------------
// smem: Kt[64][200](+64 slack), Vs[200][64], Pw[8][4][200], Qs[8][4][64]
#define ATTN_SMEM_FLOATS (64 * 200 + 64 + 200 * 64 + 8 * 4 * 200 + 8 * 4 * 64)
#define ATTN_SMEM_BYTES  (ATTN_SMEM_FLOATS * 4)

__global__ __launch_bounds__(256) void attn_kernel(float* __restrict__ out) {
    extern __shared__ float sm[];
    float* Kt = sm;                          // transposed K, pitch 200
    float* Vs = Kt + 64 * 200 + 64;          // V row-major [200][64] (rows>=197 zero)
    float* Pw = Vs + 200 * 64;               // per-warp probs [8][4][200]
    float* Qs = Pw + 8 * 4 * 200;            // per-warp q rows [8][4][64]

    int bh = blockIdx.x;
    int b = bh / NHEADS, h = bh % NHEADS;
    int tid = threadIdx.x, lane = tid & 31, w = tid >> 5;

    const float* Kg = g_K + (size_t)b * LKV * CDIM + h * HDIM;
    const float* Vg = g_V + (size_t)b * LKV * CDIM + h * HDIM;
    const float* Qg = g_Q + (size_t)b * LQ  * CDIM + h * HDIM;

    // load K (transposed) and V (rows 197..199 zeroed)
    for (int i = tid; i < 200 * 16; i += 256) {
        int r = i >> 4, c4 = (i & 15) << 2;
        float4 kv, vv;
        if (r < LKV) {
            kv = *(const float4*)(Kg + (size_t)r * CDIM + c4);
            vv = *(const float4*)(Vg + (size_t)r * CDIM + c4);
        } else {
            kv = make_float4(0.f, 0.f, 0.f, 0.f);
            vv = kv;
        }
        Kt[(c4 + 0) * 200 + r] = kv.x;
        Kt[(c4 + 1) * 200 + r] = kv.y;
        Kt[(c4 + 2) * 200 + r] = kv.z;
        Kt[(c4 + 3) * 200 + r] = kv.w;
        *(float4*)&Vs[r * 64 + c4] = vv;
    }
    __syncthreads();

    float* Pww = Pw + w * 4 * 200;
    float* Qsw = Qs + w * 4 * 64;

    for (int g = w; g * 4 < LQ; g += 8) {
        int t0 = g * 4;
        // load 4 q rows (pre-scaled); invalid rows -> 0
#pragma unroll
        for (int r = 0; r < 4; r++) {
            int t = t0 + r;
            float q0 = 0.f, q1 = 0.f;
            if (t < LQ) {
                q0 = Qg[(size_t)t * CDIM + lane] * QSCALE;
                q1 = Qg[(size_t)t * CDIM + 32 + lane] * QSCALE;
            }
            Qsw[r * 64 + lane]      = q0;
            Qsw[r * 64 + 32 + lane] = q1;
        }
        __syncwarp();

        // scores: lane owns keys j = lane + 32n, n<7
        float sc[7][4];
#pragma unroll
        for (int n = 0; n < 7; n++)
#pragma unroll
            for (int r = 0; r < 4; r++) sc[n][r] = 0.f;

#pragma unroll 2
        for (int d = 0; d < 64; d++) {
            float kd[7];
#pragma unroll
            for (int n = 0; n < 7; n++) kd[n] = Kt[d * 200 + lane + 32 * n];
            float qr[4];
#pragma unroll
            for (int r = 0; r < 4; r++) qr[r] = Qsw[r * 64 + d];
#pragma unroll
            for (int n = 0; n < 7; n++)
#pragma unroll
                for (int r = 0; r < 4; r++)
                    sc[n][r] = fmaf(kd[n], qr[r], sc[n][r]);
        }

        // masked softmax per row
#pragma unroll
        for (int r = 0; r < 4; r++) {
            float mx = -1e30f;
#pragma unroll
            for (int n = 0; n < 7; n++) {
                int j = lane + 32 * n;
                if (j < LKV) mx = fmaxf(mx, sc[n][r]);
            }
#pragma unroll
            for (int off = 16; off > 0; off >>= 1)
                mx = fmaxf(mx, __shfl_xor_sync(0xffffffffu, mx, off));
            float e[7];
            float s = 0.f;
#pragma unroll
            for (int n = 0; n < 7; n++) {
                int j = lane + 32 * n;
                e[n] = (j < LKV) ? __expf(sc[n][r] - mx) : 0.f;
                s += e[n];
            }
#pragma unroll
            for (int off = 16; off > 0; off >>= 1)
                s += __shfl_xor_sync(0xffffffffu, s, off);
            float inv = 1.f / s;
#pragma unroll
            for (int n = 0; n < 7; n++) {
                int j = lane + 32 * n;
                if (j < 200) Pww[r * 200 + j] = e[n] * inv;
            }
        }
        __syncwarp();

        // ctx = probs @ V ; lane owns dims d = lane*2, lane*2+1
        float a0[4] = {0.f, 0.f, 0.f, 0.f};
        float a1[4] = {0.f, 0.f, 0.f, 0.f};
        for (int j4 = 0; j4 < 200; j4 += 4) {
            float4 p[4];
#pragma unroll
            for (int r = 0; r < 4; r++) p[r] = *(const float4*)&Pww[r * 200 + j4];
#pragma unroll
            for (int jj = 0; jj < 4; jj++) {
                float2 v = *(const float2*)&Vs[(j4 + jj) * 64 + lane * 2];
#pragma unroll
                for (int r = 0; r < 4; r++) {
                    float pj = (jj == 0) ? p[r].x : (jj == 1) ? p[r].y
                              : (jj == 2) ? p[r].z : p[r].w;
                    a0[r] = fmaf(pj, v.x, a0[r]);
                    a1[r] = fmaf(pj, v.y, a1[r]);
                }
            }
        }
#pragma unroll
        for (int r = 0; r < 4; r++) {
            int t = t0 + r;
            if (t < LQ) {
                float2 o;
                o.x = a0[r];
                o.y = a1[r];
                *(float2*)(out + ((size_t)b * LQ + t) * CDIM + h * HDIM + lane * 2) = o;
            }
        }
        __syncwarp();   // protect Pww/Qsw before next group's overwrite
    }
}

// ---------------- entry point ----------------
extern "C" void kernel_launch(void* const* d_in, const int* in_sizes, int n_in,
                              void* d_out, int out_size) {
    (void)in_sizes; (void)n_in; (void)out_size;
    const float* hs   = (const float*)d_in[0];
    // d_in[1] = height, d_in[2] = width (fixed 28x28 by problem setup)
    const float* wdwq = (const float*)d_in[3];
    const float* gq   = (const float*)d_in[4];
    const float* beq  = (const float*)d_in[5];
    const float* mq   = (const float*)d_in[6];
    const float* vq   = (const float*)d_in[7];
    const float* Wq   = (const float*)d_in[8];
    const float* bq   = (const float*)d_in[9];
    const float* wdwk = (const float*)d_in[10];
    const float* gk   = (const float*)d_in[11];
    const float* bek  = (const float*)d_in[12];
    const float* mk   = (const float*)d_in[13];
    const float* vk   = (const float*)d_in[14];
    const float* Wk   = (const float*)d_in[15];
    const float* bk   = (const float*)d_in[16];
    const float* wdwv = (const float*)d_in[17];
    const float* gv   = (const float*)d_in[18];
    const float* bev  = (const float*)d_in[19];
    const float* mv   = (const float*)d_in[20];
    const float* vv   = (const float*)d_in[21];
    const float* Wv   = (const float*)d_in[22];
    const float* bv   = (const float*)d_in[23];
    float* out = (float*)d_out;

    cudaFuncSetAttribute(attn_kernel,
                         cudaFuncAttributeMaxDynamicSharedMemorySize,
                         ATTN_SMEM_BYTES);

    cls_copy_kernel<<<BATCH, CDIM>>>(hs);
    conv_q_kernel<<<BATCH * HIN * WIN, CDIM>>>(hs, wdwq, gq, beq, mq, vq);
    conv_kv_kernel<<<BATCH * 196, CDIM>>>(hs, wdwk, gk, bek, mk, vk,
                                              wdwv, gv, bev, mv, vv);
    gemm_bias_kernel<0><<<dim3(3, LQ),  256>>>(Wq, bq);   // M = 64*785 = 785 tiles
    gemm_bias_kernel<1><<<dim3(3, LKV), 256>>>(Wk, bk);   // M = 64*197 = 197 tiles
    gemm_bias_kernel<2><<<dim3(3, LKV), 256>>>(Wv, bv);
    attn_kernel<<<BATCH * NHEADS, 256, ATTN_SMEM_BYTES>>>(out);
}

// round 3
// speedup vs baseline: 1.3549x; 1.3549x over previous
#include <cuda_runtime.h>
#include <math.h>
#include <stdint.h>

#define BATCH  64
#define CDIM   384
#define HIN    28
#define WIN    28
#define LQ     785
#define LKV    197
#define NHEADS 6
#define HDIM   64
#define EPSB   1e-5f
#define QSCALE 0.051031036307982884f

#define MQP   50304            // 393 * 128
#define MKVP  12672            // 99 * 128
#define QTILES  393
#define KVTILES 99
#define MTILES  (QTILES + 2 * KVTILES)   // 591

// ---------------- device scratch ----------------
__device__ float g_qc[MQP  * CDIM];
__device__ float g_kc[MKVP * CDIM];
__device__ float g_vc[MKVP * CDIM];
__device__ float g_Q [MQP  * CDIM];
__device__ float g_K [MKVP * CDIM];
__device__ float g_V [MKVP * CDIM];
__device__ float g_WT[3 * CDIM * CDIM];   // W transposed: [n][k], tf32-rounded

// ---------------- helpers ----------------
__device__ __forceinline__ float tf32r(float x) {
    uint32_t u;
    asm("cvt.rna.tf32.f32 %0, %1;" : "=r"(u) : "f"(x));
    return __uint_as_float(u);
}
__device__ __forceinline__ uint32_t fu(float x) { return __float_as_uint(x); }

// D += A(16x8,row) * B(8x8,col)   tf32
__device__ __forceinline__ void mma8(float* d, const uint32_t* a, const uint32_t* b) {
    asm volatile(
        "mma.sync.aligned.m16n8k8.row.col.f32.tf32.tf32.f32 "
        "{%0,%1,%2,%3}, {%4,%5,%6,%7}, {%8,%9}, {%0,%1,%2,%3};"
        : "+f"(d[0]), "+f"(d[1]), "+f"(d[2]), "+f"(d[3])
        : "r"(a[0]), "r"(a[1]), "r"(a[2]), "r"(a[3]), "r"(b[0]), "r"(b[1]));
}

// ---------------- cls token copy (tf32-rounded) ----------------
__global__ void cls_copy_kernel(const float* __restrict__ hs) {
    int b = blockIdx.x, c = threadIdx.x;
    float v = tf32r(hs[(size_t)b * LQ * CDIM + c]);
    g_qc[(size_t)b * LQ  * CDIM + c] = v;
    g_kc[(size_t)b * LKV * CDIM + c] = v;
    g_vc[(size_t)b * LKV * CDIM + c] = v;
}

// ---------------- depthwise 3x3 s1 conv + BN (q) ----------------
__global__ __launch_bounds__(CDIM) void conv_q_kernel(
    const float* __restrict__ hs, const float* __restrict__ wdw,
    const float* __restrict__ gam, const float* __restrict__ bet,
    const float* __restrict__ mean, const float* __restrict__ var) {
    int c = threadIdx.x;
    int pos = blockIdx.x % (HIN * WIN);
    int b   = blockIdx.x / (HIN * WIN);
    int oh = pos / WIN, ow = pos % WIN;
    const float* xb = hs + (size_t)b * LQ * CDIM + CDIM;
    float acc = 0.f;
#pragma unroll
    for (int kh = 0; kh < 3; kh++) {
        int ih = oh + kh - 1;
        if ((unsigned)ih >= HIN) continue;
#pragma unroll
        for (int kw = 0; kw < 3; kw++) {
            int iw = ow + kw - 1;
            if ((unsigned)iw >= WIN) continue;
            acc = fmaf(xb[(ih * WIN + iw) * CDIM + c], wdw[(kh * 3 + kw) * CDIM + c], acc);
        }
    }
    float s = gam[c] * rsqrtf(var[c] + EPSB);
    g_qc[(size_t)b * LQ * CDIM + (size_t)(1 + pos) * CDIM + c] =
        tf32r(acc * s + (bet[c] - mean[c] * s));
}

// ---------------- depthwise 3x3 s2 conv + BN (k,v) ----------------
__global__ __launch_bounds__(CDIM) void conv_kv_kernel(
    const float* __restrict__ hs,
    const float* __restrict__ wk, const float* __restrict__ gk,
    const float* __restrict__ bek, const float* __restrict__ mk,
    const float* __restrict__ vk,
    const float* __restrict__ wv, const float* __restrict__ gv,
    const float* __restrict__ bev, const float* __restrict__ mv,
    const float* __restrict__ vvv) {
    int c = threadIdx.x;
    int pos = blockIdx.x % 196;
    int b   = blockIdx.x / 196;
    int oh = pos / 14, ow = pos % 14;
    const float* xb = hs + (size_t)b * LQ * CDIM + CDIM;
    float ak = 0.f, av = 0.f;
#pragma unroll
    for (int kh = 0; kh < 3; kh++) {
        int ih = oh * 2 + kh - 1;
        if ((unsigned)ih >= HIN) continue;
#pragma unroll
        for (int kw = 0; kw < 3; kw++) {
            int iw = ow * 2 + kw - 1;
            if ((unsigned)iw >= WIN) continue;
            float x = xb[(ih * WIN + iw) * CDIM + c];
            ak = fmaf(x, wk[(kh * 3 + kw) * CDIM + c], ak);
            av = fmaf(x, wv[(kh * 3 + kw) * CDIM + c], av);
        }
    }
    float sk = gk[c] * rsqrtf(vk[c]  + EPSB);
    float sv = gv[c] * rsqrtf(vvv[c] + EPSB);
    size_t o = (size_t)b * LKV * CDIM + (size_t)(1 + pos) * CDIM + c;
    g_kc[o] = tf32r(ak * sk + (bek[c] - mk[c] * sk));
    g_vc[o] = tf32r(av * sv + (bev[c] - mv[c] * sv));
}

// ---------------- W transpose (tf32-rounded): g_WT[n][k] = W[k][n] ----------------
__global__ void transpose_w_kernel(const float* __restrict__ Wq,
                                   const float* __restrict__ Wk,
                                   const float* __restrict__ Wv) {
    __shared__ float t[32][33];
    int z = blockIdx.z;
    const float* src = (z == 0) ? Wq : (z == 1) ? Wk : Wv;
    float* dst = g_WT + (size_t)z * CDIM * CDIM;
    int tx = threadIdx.x, ty = threadIdx.y;
    int x = blockIdx.x * 32 + tx;
    int y0 = blockIdx.y * 32;
#pragma unroll
    for (int r = 0; r < 32; r += 8)
        t[ty + r][tx] = src[(size_t)(y0 + ty + r) * CDIM + x];
    __syncthreads();
    int n = blockIdx.x * 32 + ty;
#pragma unroll
    for (int r = 0; r < 32; r += 8)
        dst[(size_t)(n + r) * CDIM + y0 + tx] = tf32r(t[tx][ty + r]);
}

// ---------------- tf32 mma GEMM: C = A(Mx384) @ W + bias (tf32-rounded out) ----------------
// CTA: 128M x 128N, BK=32 double-buffered. 8 warps = 4M x 2N, warp tile 32x64.
#define GPITCH 36
#define GEMM_SMEM (2 * 2 * 128 * GPITCH * 4)   // As+Bs, 2 buffers: 73728 B

__global__ __launch_bounds__(256, 2) void gemm_mma_kernel(
    const float* __restrict__ bq, const float* __restrict__ bk,
    const float* __restrict__ bv) {
    extern __shared__ float gsm[];
    float* As = gsm;                       // [2][128*36]
    float* Bs = gsm + 2 * 128 * GPITCH;    // [2][128*36]

    int mt = blockIdx.y, ntile = blockIdx.x;
    int sel, mloc;
    if (mt < QTILES)                 { sel = 0; mloc = mt; }
    else if (mt < QTILES + KVTILES)  { sel = 1; mloc = mt - QTILES; }
    else                             { sel = 2; mloc = mt - QTILES - KVTILES; }
    const float* A    = (sel == 0) ? g_qc : (sel == 1) ? g_kc : g_vc;
    float*       C    = (sel == 0) ? g_Q  : (sel == 1) ? g_K  : g_V;
    const float* WT   = g_WT + (size_t)sel * CDIM * CDIM;
    const float* bias = (sel == 0) ? bq : (sel == 1) ? bk : bv;
    const int m0 = mloc * 128, n0 = ntile * 128;

    const int tid = threadIdx.x, lane = tid & 31, wid = tid >> 5;
    const int gid = lane >> 2, tig = lane & 3;
    const int wm = wid & 3, wn = wid >> 2;

    const int lr = tid >> 3;            // 0..31
    const int lc = (tid & 7) << 2;      // 0,4,...,28
    const float* Ag = A  + ((size_t)(m0 + lr)) * CDIM + lc;
    const float* Bg = WT + ((size_t)(n0 + lr)) * CDIM + lc;

    float acc[2][8][4];
#pragma unroll
    for (int i = 0; i < 2; i++)
#pragma unroll
        for (int j = 0; j < 8; j++)
#pragma unroll
            for (int c = 0; c < 4; c++) acc[i][j][c] = 0.f;

    // stage 0
#pragma unroll
    for (int i = 0; i < 4; i++) {
        float4 va = *(const float4*)(Ag + (size_t)(32 * i) * CDIM);
        float4 vb = *(const float4*)(Bg + (size_t)(32 * i) * CDIM);
        *(float4*)&As[(lr + 32 * i) * GPITCH + lc] = va;
        *(float4*)&Bs[(lr + 32 * i) * GPITCH + lc] = vb;
    }
    __syncthreads();

#pragma unroll 1
    for (int s = 0; s < 12; s++) {
        int buf = s & 1;
        if (s + 1 < 12) {
            int nbuf = (s + 1) & 1;
            int k0 = (s + 1) * 32;
#pragma unroll
            for (int i = 0; i < 4; i++) {
                float4 va = *(const float4*)(Ag + (size_t)(32 * i) * CDIM + k0);
                float4 vb = *(const float4*)(Bg + (size_t)(32 * i) * CDIM + k0);
                *(float4*)&As[nbuf * 128 * GPITCH + (lr + 32 * i) * GPITCH + lc] = va;
                *(float4*)&Bs[nbuf * 128 * GPITCH + (lr + 32 * i) * GPITCH + lc] = vb;
            }
        }
        const float* Ab = As + buf * 128 * GPITCH;
        const float* Bb = Bs + buf * 128 * GPITCH;
#pragma unroll
        for (int kk = 0; kk < 4; kk++) {
            int kb = kk * 8;
            uint32_t a[2][4];
#pragma unroll
            for (int m2 = 0; m2 < 2; m2++) {
                int mr = (wm * 32 + m2 * 16 + gid) * GPITCH;
                a[m2][0] = fu(Ab[mr + kb + tig]);
                a[m2][1] = fu(Ab[mr + 8 * GPITCH + kb + tig]);
                a[m2][2] = fu(Ab[mr + kb + tig + 4]);
                a[m2][3] = fu(Ab[mr + 8 * GPITCH + kb + tig + 4]);
            }
#pragma unroll
            for (int nt = 0; nt < 8; nt++) {
                int nr = (wn * 64 + nt * 8 + gid) * GPITCH;
                uint32_t bb[2] = { fu(Bb[nr + kb + tig]), fu(Bb[nr + kb + tig + 4]) };
                mma8(acc[0][nt], a[0], bb);
                mma8(acc[1][nt], a[1], bb);
            }
        }
        __syncthreads();
    }

    // epilogue: bias add, tf32-round (outputs feed attention mma)
#pragma unroll
    for (int m2 = 0; m2 < 2; m2++) {
        int row = m0 + wm * 32 + m2 * 16 + gid;
#pragma unroll
        for (int nt = 0; nt < 8; nt++) {
            int col = n0 + wn * 64 + nt * 8 + 2 * tig;
            float b0 = bias[col], b1 = bias[col + 1];
            float2 v0, v1;
            v0.x = tf32r(acc[m2][nt][0] + b0);
            v0.y = tf32r(acc[m2][nt][1] + b1);
            v1.x = tf32r(acc[m2][nt][2] + b0);
            v1.y = tf32r(acc[m2][nt][3] + b1);
            *(float2*)(C + (size_t)row * CDIM + col)       = v0;
            *(float2*)(C + (size_t)(row + 8) * CDIM + col) = v1;
        }
    }
}

// ---------------- attention with tf32 mma: one CTA per (b,h) ----------------
#define NKVP 208
#define KPCH 68     // Ks / Qs pitch
#define SPCH 212    // Ssm / VsT pitch
#define ATTN_SMEM ((NKVP * KPCH + 64 * SPCH + 64 * KPCH + 64 * SPCH) * 4)
#define NQB 13      // ceil(785/64)

__global__ __launch_bounds__(256, 1) void attn_mma_kernel(float* __restrict__ out) {
    extern __shared__ float sm[];
    float* Ks  = sm;                     // [208][68]  K rows (n), k contiguous
    float* VsT = Ks + NKVP * KPCH;       // [64][212]  V^T: rows=dim, cols=kv
    float* Qs  = VsT + 64 * SPCH;        // [64][68]
    float* Ssm = Qs + 64 * KPCH;         // [64][212]  scores -> probs

    int bh = blockIdx.x;
    int b = bh / NHEADS, h = bh % NHEADS;
    int tid = threadIdx.x, lane = tid & 31, wid = tid >> 5;
    int gid = lane >> 2, tig = lane & 3;
    int wm = wid & 3, wn = wid >> 2;

    const float* Kg = g_K + ((size_t)b * LKV) * CDIM + h * HDIM;
    const float* Vg = g_V + ((size_t)b * LKV) * CDIM + h * HDIM;
    const float* Qg = g_Q + ((size_t)b * LQ)  * CDIM + h * HDIM;

    // load K (rows >=197 zero) and V transposed (kv cols >=197 zero)
    for (int i = tid; i < NKVP * 16; i += 256) {
        int n = i >> 4, k4 = (i & 15) << 2;
        float4 kv = make_float4(0.f, 0.f, 0.f, 0.f), vv = kv;
        if (n < LKV) {
            kv = *(const float4*)(Kg + (size_t)n * CDIM + k4);
            vv = *(const float4*)(Vg + (size_t)n * CDIM + k4);
        }
        *(float4*)&Ks[n * KPCH + k4] = kv;
        VsT[(k4 + 0) * SPCH + n] = vv.x;
        VsT[(k4 + 1) * SPCH + n] = vv.y;
        VsT[(k4 + 2) * SPCH + n] = vv.z;
        VsT[(k4 + 3) * SPCH + n] = vv.w;
    }
    __syncthreads();

    const int mrow = wm * 16 + gid;

#pragma unroll 1
    for (int qb = 0; qb < NQB; qb++) {
        int t0 = qb * 64;
        // load 64 q rows (invalid -> 0)
        for (int i = tid; i < 64 * 16; i += 256) {
            int r = i >> 4, k4 = (i & 15) << 2;
            int t = t0 + r;
            float4 v = make_float4(0.f, 0.f, 0.f, 0.f);
            if (t < LQ) v = *(const float4*)(Qg + (size_t)t * CDIM + k4);
            *(float4*)&Qs[r * KPCH + k4] = v;
        }
        __syncthreads();

        // ---- scores: warp tile 16M x 104N (13 n-tiles), K=64 ----
        float acc[13][4];
#pragma unroll
        for (int nt = 0; nt < 13; nt++)
#pragma unroll
            for (int c = 0; c < 4; c++) acc[nt][c] = 0.f;

#pragma unroll
        for (int kk = 0; kk < 8; kk++) {
            int kb = kk * 8;
            uint32_t a[4];
            a[0] = fu(Qs[mrow * KPCH + kb + tig]);
            a[1] = fu(Qs[(mrow + 8) * KPCH + kb + tig]);
            a[2] = fu(Qs[mrow * KPCH + kb + tig + 4]);
            a[3] = fu(Qs[(mrow + 8) * KPCH + kb + tig + 4]);
#pragma unroll
            for (int nt = 0; nt < 13; nt++) {
                int nr = (wn * 104 + nt * 8 + gid) * KPCH;
                uint32_t bb[2] = { fu(Ks[nr + kb + tig]), fu(Ks[nr + kb + tig + 4]) };
                mma8(acc[nt], a, bb);
            }
        }
#pragma unroll
        for (int nt = 0; nt < 13; nt++) {
            int n = wn * 104 + nt * 8 + 2 * tig;
            float2 v0 = { acc[nt][0], acc[nt][1] };
            float2 v1 = { acc[nt][2], acc[nt][3] };
            *(float2*)&Ssm[mrow * SPCH + n]       = v0;
            *(float2*)&Ssm[(mrow + 8) * SPCH + n] = v1;
        }
        __syncthreads();

        // ---- masked softmax (warp wid owns rows wid*8 .. wid*8+7) ----
#pragma unroll 1
        for (int rr = 0; rr < 8; rr++) {
            int row = wid * 8 + rr;
            float x[7], mx = -1e30f;
#pragma unroll
            for (int i = 0; i < 7; i++) {
                int j = lane + 32 * i;
                x[i] = (j < LKV) ? Ssm[row * SPCH + j] * QSCALE : -1e30f;
                mx = fmaxf(mx, x[i]);
            }
#pragma unroll
            for (int off = 16; off > 0; off >>= 1)
                mx = fmaxf(mx, __shfl_xor_sync(0xffffffffu, mx, off));
            float e[7], ssum = 0.f;
#pragma unroll
            for (int i = 0; i < 7; i++) {
                int j = lane + 32 * i;
                e[i] = (j < LKV) ? __expf(x[i] - mx) : 0.f;
                ssum += e[i];
            }
#pragma unroll
            for (int off = 16; off > 0; off >>= 1)
                ssum += __shfl_xor_sync(0xffffffffu, ssum, off);
            float inv = 1.f / ssum;
#pragma unroll
            for (int i = 0; i < 7; i++) {
                int j = lane + 32 * i;
                if (j < NKVP) Ssm[row * SPCH + j] = tf32r(e[i] * inv);
            }
        }
        __syncthreads();

        // ---- PV: warp tile 16M x 32N (4 n-tiles), K=208 ----
        float acc2[4][4];
#pragma unroll
        for (int nt = 0; nt < 4; nt++)
#pragma unroll
            for (int c = 0; c < 4; c++) acc2[nt][c] = 0.f;

#pragma unroll 2
        for (int kk = 0; kk < 26; kk++) {
            int kb = kk * 8;
            uint32_t a[4];
            a[0] = fu(Ssm[mrow * SPCH + kb + tig]);
            a[1] = fu(Ssm[(mrow + 8) * SPCH + kb + tig]);
            a[2] = fu(Ssm[mrow * SPCH + kb + tig + 4]);
            a[3] = fu(Ssm[(mrow + 8) * SPCH + kb + tig + 4]);
#pragma unroll
            for (int nt = 0; nt < 4; nt++) {
                int nr = (wn * 32 + nt * 8 + gid) * SPCH;
                uint32_t bb[2] = { fu(VsT[nr + kb + tig]), fu(VsT[nr + kb + tig + 4]) };
                mma8(acc2[nt], a, bb);
            }
        }

        // ---- write ctx ----
        int t = t0 + mrow;
#pragma unroll
        for (int nt = 0; nt < 4; nt++) {
            int col = h * HDIM + wn * 32 + nt * 8 + 2 * tig;
            if (t < LQ) {
                float2 v = { acc2[nt][0], acc2[nt][1] };
                *(float2*)(out + ((size_t)b * LQ + t) * CDIM + col) = v;
            }
            if (t + 8 < LQ) {
                float2 v = { acc2[nt][2], acc2[nt][3] };
                *(float2*)(out + ((size_t)b * LQ + t + 8) * CDIM + col) = v;
            }
        }
        __syncthreads();   // before next q-block overwrites Qs/Ssm
    }
}

// ---------------- entry point ----------------
extern "C" void kernel_launch(void* const* d_in, const int* in_sizes, int n_in,
                              void* d_out, int out_size) {
    (void)in_sizes; (void)n_in; (void)out_size;
    const float* hs   = (const float*)d_in[0];
    const float* wdwq = (const float*)d_in[3];
    const float* gq   = (const float*)d_in[4];
    const float* beq  = (const float*)d_in[5];
    const float* mq   = (const float*)d_in[6];
    const float* vq   = (const float*)d_in[7];
    const float* Wq   = (const float*)d_in[8];
    const float* bq   = (const float*)d_in[9];
    const float* wdwk = (const float*)d_in[10];
    const float* gk   = (const float*)d_in[11];
    const float* bek  = (const float*)d_in[12];
    const float* mk   = (const float*)d_in[13];
    const float* vk   = (const float*)d_in[14];
    const float* Wk   = (const float*)d_in[15];
    const float* bk   = (const float*)d_in[16];
    const float* wdwv = (const float*)d_in[17];
    const float* gv   = (const float*)d_in[18];
    const float* bev  = (const float*)d_in[19];
    const float* mv   = (const float*)d_in[20];
    const float* vv   = (const float*)d_in[21];
    const float* Wv   = (const float*)d_in[22];
    const float* bv   = (const float*)d_in[23];
    float* out = (float*)d_out;

    cudaFuncSetAttribute(gemm_mma_kernel,
                         cudaFuncAttributeMaxDynamicSharedMemorySize, GEMM_SMEM);
    cudaFuncSetAttribute(attn_mma_kernel,
                         cudaFuncAttributeMaxDynamicSharedMemorySize, ATTN_SMEM);

    cls_copy_kernel<<<BATCH, CDIM>>>(hs);
    conv_q_kernel<<<BATCH * HIN * WIN, CDIM>>>(hs, wdwq, gq, beq, mq, vq);
    conv_kv_kernel<<<BATCH * 196, CDIM>>>(hs, wdwk, gk, bek, mk, vk,
                                          wdwv, gv, bev, mv, vv);
    transpose_w_kernel<<<dim3(12, 12, 3), dim3(32, 8)>>>(Wq, Wk, Wv);
    gemm_mma_kernel<<<dim3(3, MTILES), 256, GEMM_SMEM>>>(bq, bk, bv);
    attn_mma_kernel<<<BATCH * NHEADS, 256, ATTN_SMEM>>>(out);
}

// round 4
// speedup vs baseline: 2.3592x; 1.7412x over previous
#include <cuda_runtime.h>
#include <math.h>
#include <stdint.h>

#define BATCH  64
#define CDIM   384
#define HIN    28
#define WIN    28
#define LQ     785
#define LKV    197
#define NHEADS 6
#define HDIM   64
#define EPSB   1e-5f
#define QSCALE 0.051031036307982884f

#define MQP   50304            // 393 * 128
#define MKVP  12672            // 99 * 128
#define QTILES  393
#define KVTILES 99
#define MTILES  (QTILES + 2 * KVTILES)   // 591

// ---------------- device scratch ----------------
__device__ float g_qc[MQP  * CDIM];
__device__ float g_kc[MKVP * CDIM];
__device__ float g_vc[MKVP * CDIM];
__device__ float g_Q [MQP  * CDIM];
__device__ float g_K [MKVP * CDIM];
__device__ float g_V [MKVP * CDIM];
__device__ float g_WT[3 * CDIM * CDIM];   // W transposed: [n][k], tf32-rounded

// ---------------- helpers ----------------
__device__ __forceinline__ float tf32r(float x) {
    uint32_t u;
    asm("cvt.rna.tf32.f32 %0, %1;" : "=r"(u) : "f"(x));
    return __uint_as_float(u);
}
__device__ __forceinline__ uint32_t fu(float x) { return __float_as_uint(x); }
__device__ __forceinline__ uint32_t smem_u32(const void* p) {
    uint32_t a;
    asm("{ .reg .u64 t; cvta.to.shared.u64 t, %1; cvt.u32.u64 %0, t; }" : "=r"(a) : "l"(p));
    return a;
}
__device__ __forceinline__ void cp16(uint32_t s, const void* g) {
    asm volatile("cp.async.cg.shared.global [%0], [%1], 16;" :: "r"(s), "l"(g) : "memory");
}
__device__ __forceinline__ void cp16z(uint32_t s, const void* g, int srcsize) {
    asm volatile("cp.async.cg.shared.global [%0], [%1], 16, %2;"
                 :: "r"(s), "l"(g), "r"(srcsize) : "memory");
}
#define CP_COMMIT() asm volatile("cp.async.commit_group;" ::: "memory")
template <int N>
__device__ __forceinline__ void cp_wait() {
    asm volatile("cp.async.wait_group %0;" :: "n"(N) : "memory");
}

// D += A(16x8,row) * B(8x8,col)   tf32
__device__ __forceinline__ void mma8(float* d, const uint32_t* a, const uint32_t* b) {
    asm volatile(
        "mma.sync.aligned.m16n8k8.row.col.f32.tf32.tf32.f32 "
        "{%0,%1,%2,%3}, {%4,%5,%6,%7}, {%8,%9}, {%0,%1,%2,%3};"
        : "+f"(d[0]), "+f"(d[1]), "+f"(d[2]), "+f"(d[3])
        : "r"(a[0]), "r"(a[1]), "r"(a[2]), "r"(a[3]), "r"(b[0]), "r"(b[1]));
}

// ---------------- cls token copy (tf32-rounded) ----------------
__global__ void cls_copy_kernel(const float* __restrict__ hs) {
    int b = blockIdx.x, c = threadIdx.x;
    float v = tf32r(hs[(size_t)b * LQ * CDIM + c]);
    g_qc[(size_t)b * LQ  * CDIM + c] = v;
    g_kc[(size_t)b * LKV * CDIM + c] = v;
    g_vc[(size_t)b * LKV * CDIM + c] = v;
}

// ---------------- depthwise 3x3 s1 conv + BN (q) ----------------
__global__ __launch_bounds__(CDIM) void conv_q_kernel(
    const float* __restrict__ hs, const float* __restrict__ wdw,
    const float* __restrict__ gam, const float* __restrict__ bet,
    const float* __restrict__ mean, const float* __restrict__ var) {
    int c = threadIdx.x;
    int pos = blockIdx.x % (HIN * WIN);
    int b   = blockIdx.x / (HIN * WIN);
    int oh = pos / WIN, ow = pos % WIN;
    const float* xb = hs + (size_t)b * LQ * CDIM + CDIM;
    float acc = 0.f;
#pragma unroll
    for (int kh = 0; kh < 3; kh++) {
        int ih = oh + kh - 1;
        if ((unsigned)ih >= HIN) continue;
#pragma unroll
        for (int kw = 0; kw < 3; kw++) {
            int iw = ow + kw - 1;
            if ((unsigned)iw >= WIN) continue;
            acc = fmaf(xb[(ih * WIN + iw) * CDIM + c], wdw[(kh * 3 + kw) * CDIM + c], acc);
        }
    }
    float s = gam[c] * rsqrtf(var[c] + EPSB);
    g_qc[(size_t)b * LQ * CDIM + (size_t)(1 + pos) * CDIM + c] =
        tf32r(acc * s + (bet[c] - mean[c] * s));
}

// ---------------- depthwise 3x3 s2 conv + BN (k,v) ----------------
__global__ __launch_bounds__(CDIM) void conv_kv_kernel(
    const float* __restrict__ hs,
    const float* __restrict__ wk, const float* __restrict__ gk,
    const float* __restrict__ bek, const float* __restrict__ mk,
    const float* __restrict__ vk,
    const float* __restrict__ wv, const float* __restrict__ gv,
    const float* __restrict__ bev, const float* __restrict__ mv,
    const float* __restrict__ vvv) {
    int c = threadIdx.x;
    int pos = blockIdx.x % 196;
    int b   = blockIdx.x / 196;
    int oh = pos / 14, ow = pos % 14;
    const float* xb = hs + (size_t)b * LQ * CDIM + CDIM;
    float ak = 0.f, av = 0.f;
#pragma unroll
    for (int kh = 0; kh < 3; kh++) {
        int ih = oh * 2 + kh - 1;
        if ((unsigned)ih >= HIN) continue;
#pragma unroll
        for (int kw = 0; kw < 3; kw++) {
            int iw = ow * 2 + kw - 1;
            if ((unsigned)iw >= WIN) continue;
            float x = xb[(ih * WIN + iw) * CDIM + c];
            ak = fmaf(x, wk[(kh * 3 + kw) * CDIM + c], ak);
            av = fmaf(x, wv[(kh * 3 + kw) * CDIM + c], av);
        }
    }
    float sk = gk[c] * rsqrtf(vk[c]  + EPSB);
    float sv = gv[c] * rsqrtf(vvv[c] + EPSB);
    size_t o = (size_t)b * LKV * CDIM + (size_t)(1 + pos) * CDIM + c;
    g_kc[o] = tf32r(ak * sk + (bek[c] - mk[c] * sk));
    g_vc[o] = tf32r(av * sv + (bev[c] - mv[c] * sv));
}

// ---------------- W transpose (tf32-rounded): g_WT[n][k] = W[k][n] ----------------
__global__ void transpose_w_kernel(const float* __restrict__ Wq,
                                   const float* __restrict__ Wk,
                                   const float* __restrict__ Wv) {
    __shared__ float t[32][33];
    int z = blockIdx.z;
    const float* src = (z == 0) ? Wq : (z == 1) ? Wk : Wv;
    float* dst = g_WT + (size_t)z * CDIM * CDIM;
    int tx = threadIdx.x, ty = threadIdx.y;
    int x = blockIdx.x * 32 + tx;
    int y0 = blockIdx.y * 32;
#pragma unroll
    for (int r = 0; r < 32; r += 8)
        t[ty + r][tx] = src[(size_t)(y0 + ty + r) * CDIM + x];
    __syncthreads();
    int n = blockIdx.x * 32 + ty;
#pragma unroll
    for (int r = 0; r < 32; r += 8)
        dst[(size_t)(n + r) * CDIM + y0 + tx] = tf32r(t[tx][ty + r]);
}

// ---------------- tf32 mma GEMM, 3-stage cp.async pipeline ----------------
// CTA: 128M x 128N, BK=32, 3 stages. 8 warps = 4M x 2N, warp tile 32x64.
#define GPITCH  36
#define GSTAGEF (2 * 128 * GPITCH)          // floats per stage (A then B)
#define GEMM_SMEM (3 * GSTAGEF * 4)         // 110,592 B

__global__ __launch_bounds__(256, 2) void gemm_mma_kernel(
    const float* __restrict__ bq, const float* __restrict__ bk,
    const float* __restrict__ bv) {
    extern __shared__ float gsm[];

    int mt = blockIdx.y, ntile = blockIdx.x;
    int sel, mloc;
    if (mt < QTILES)                 { sel = 0; mloc = mt; }
    else if (mt < QTILES + KVTILES)  { sel = 1; mloc = mt - QTILES; }
    else                             { sel = 2; mloc = mt - QTILES - KVTILES; }
    const float* A    = (sel == 0) ? g_qc : (sel == 1) ? g_kc : g_vc;
    float*       C    = (sel == 0) ? g_Q  : (sel == 1) ? g_K  : g_V;
    const float* WT   = g_WT + (size_t)sel * CDIM * CDIM;
    const float* bias = (sel == 0) ? bq : (sel == 1) ? bk : bv;
    const float oscale = (sel == 0) ? QSCALE : 1.0f;
    const int m0 = mloc * 128, n0 = ntile * 128;

    const int tid = threadIdx.x, lane = tid & 31, wid = tid >> 5;
    const int gid = lane >> 2, tig = lane & 3;
    const int wm = wid & 3, wn = wid >> 2;

    const int lr = tid >> 3;            // 0..31
    const int lc = (tid & 7) << 2;      // 0,4,...,28
    const float* Ag = A  + ((size_t)(m0 + lr)) * CDIM + lc;
    const float* Bg = WT + ((size_t)(n0 + lr)) * CDIM + lc;
    uint32_t sbase = smem_u32(gsm);

    float acc[2][8][4];
#pragma unroll
    for (int i = 0; i < 2; i++)
#pragma unroll
        for (int j = 0; j < 8; j++)
#pragma unroll
            for (int c = 0; c < 4; c++) acc[i][j][c] = 0.f;

    // async issue of stage s (k-chunk s)
#define G_ISSUE(s)                                                              \
    do {                                                                        \
        int st_ = (s) % 3;                                                      \
        int k0_ = (s) * 32;                                                     \
        uint32_t as_ = sbase + (uint32_t)(st_ * GSTAGEF) * 4u;                  \
        uint32_t bs_ = as_ + (uint32_t)(128 * GPITCH) * 4u;                     \
        _Pragma("unroll")                                                       \
        for (int i_ = 0; i_ < 4; i_++) {                                        \
            cp16(as_ + (uint32_t)(((lr + 32 * i_) * GPITCH + lc) * 4),          \
                 Ag + (size_t)(32 * i_) * CDIM + k0_);                          \
            cp16(bs_ + (uint32_t)(((lr + 32 * i_) * GPITCH + lc) * 4),          \
                 Bg + (size_t)(32 * i_) * CDIM + k0_);                          \
        }                                                                       \
    } while (0)

    G_ISSUE(0); CP_COMMIT();
    G_ISSUE(1); CP_COMMIT();

#pragma unroll 1
    for (int s = 0; s < 12; s++) {
        if (s <= 9)       { G_ISSUE(s + 2); CP_COMMIT(); cp_wait<2>(); }
        else if (s == 10) cp_wait<1>();
        else              cp_wait<0>();
        __syncthreads();

        const float* Ab = gsm + (s % 3) * GSTAGEF;
        const float* Bb = Ab + 128 * GPITCH;
#pragma unroll
        for (int kk = 0; kk < 4; kk++) {
            int kb = kk * 8;
            uint32_t a[2][4];
#pragma unroll
            for (int m2 = 0; m2 < 2; m2++) {
                int mr = (wm * 32 + m2 * 16 + gid) * GPITCH;
                a[m2][0] = fu(Ab[mr + kb + tig]);
                a[m2][1] = fu(Ab[mr + 8 * GPITCH + kb + tig]);
                a[m2][2] = fu(Ab[mr + kb + tig + 4]);
                a[m2][3] = fu(Ab[mr + 8 * GPITCH + kb + tig + 4]);
            }
#pragma unroll
            for (int nt = 0; nt < 8; nt++) {
                int nr = (wn * 64 + nt * 8 + gid) * GPITCH;
                uint32_t bb[2] = { fu(Bb[nr + kb + tig]), fu(Bb[nr + kb + tig + 4]) };
                mma8(acc[0][nt], a[0], bb);
                mma8(acc[1][nt], a[1], bb);
            }
        }
        __syncthreads();
    }
#undef G_ISSUE

    // epilogue: bias add, optional q-scale, tf32-round
#pragma unroll
    for (int m2 = 0; m2 < 2; m2++) {
        int row = m0 + wm * 32 + m2 * 16 + gid;
#pragma unroll
        for (int nt = 0; nt < 8; nt++) {
            int col = n0 + wn * 64 + nt * 8 + 2 * tig;
            float b0 = bias[col], b1 = bias[col + 1];
            float2 v0, v1;
            v0.x = tf32r((acc[m2][nt][0] + b0) * oscale);
            v0.y = tf32r((acc[m2][nt][1] + b1) * oscale);
            v1.x = tf32r((acc[m2][nt][2] + b0) * oscale);
            v1.y = tf32r((acc[m2][nt][3] + b1) * oscale);
            *(float2*)(C + (size_t)row * CDIM + col)       = v0;
            *(float2*)(C + (size_t)(row + 8) * CDIM + col) = v1;
        }
    }
}

// ---------------- attention, 512 threads, Q double-buffered via cp.async ----------------
#define NKVP 224
#define KPCH 68     // Ks / Qs pitch
#define SPCH 228    // Ssm / VsT pitch (mod 32 == 4 -> conflict-free frag loads)
#define NQB  13
// smem floats: Ks[224][68] + VsT[64][228] + Ssm[64][228] + Qs[2][64][68]
#define ATTN_SMEM ((NKVP * KPCH + 64 * SPCH + 64 * SPCH + 2 * 64 * KPCH) * 4)

__global__ __launch_bounds__(512, 1) void attn_mma_kernel(float* __restrict__ out) {
    extern __shared__ float sm[];
    float* Ks  = sm;                       // [224][68]  K rows (n), k contiguous
    float* VsT = Ks + NKVP * KPCH;         // [64][228]  V^T: rows=dim, cols=kv
    float* Ssm = VsT + 64 * SPCH;          // [64][228]  scores -> probs
    float* Qs  = Ssm + 64 * SPCH;          // [2][64][68]

    int bh = blockIdx.x;
    int b = bh / NHEADS, h = bh % NHEADS;
    int tid = threadIdx.x, lane = tid & 31, wid = tid >> 5;
    int gid = lane >> 2, tig = lane & 3;
    int wm = wid & 3, wn = wid >> 2;
    const int mrow = wm * 16 + gid;

    const float* Kg = g_K + ((size_t)b * LKV) * CDIM + h * HDIM;
    const float* Vg = g_V + ((size_t)b * LKV) * CDIM + h * HDIM;
    const float* Qg = g_Q + ((size_t)b * LQ)  * CDIM + h * HDIM;

    uint32_t qs_base = smem_u32(Qs);

    // load K (rows >=197 zero) and V transposed (kv cols >=197 zero)
    for (int i = tid; i < NKVP * 16; i += 512) {
        int n = i >> 4, k4 = (i & 15) << 2;
        float4 kv = make_float4(0.f, 0.f, 0.f, 0.f), vv = kv;
        if (n < LKV) {
            kv = *(const float4*)(Kg + (size_t)n * CDIM + k4);
            vv = *(const float4*)(Vg + (size_t)n * CDIM + k4);
        }
        *(float4*)&Ks[n * KPCH + k4] = kv;
        VsT[(k4 + 0) * SPCH + n] = vv.x;
        VsT[(k4 + 1) * SPCH + n] = vv.y;
        VsT[(k4 + 2) * SPCH + n] = vv.z;
        VsT[(k4 + 3) * SPCH + n] = vv.w;
    }

    // async prefetch of q-block qb into Q buffer `buf` (1024 cp16 ops / 512 thr)
#define Q_PREFETCH(qb, buf)                                                     \
    do {                                                                        \
        int t0_ = (qb) * 64;                                                    \
        _Pragma("unroll")                                                       \
        for (int j_ = 0; j_ < 2; j_++) {                                        \
            int op_ = tid * 2 + j_;                                             \
            int r_ = op_ >> 4, c4_ = (op_ & 15) << 2;                           \
            int t_ = t0_ + r_;                                                  \
            cp16z(qs_base + (uint32_t)((((buf) * 64 + r_) * KPCH + c4_) * 4),   \
                  Qg + (size_t)t_ * CDIM + c4_, (t_ < LQ) ? 16 : 0);            \
        }                                                                       \
    } while (0)

    Q_PREFETCH(0, 0);
    CP_COMMIT();

#pragma unroll 1
    for (int qb = 0; qb < NQB; qb++) {
        int qbuf = qb & 1;
        cp_wait<0>();
        __syncthreads();   // Q[qbuf] ready (and K/V on first iter; Ssm free)

        const float* Qb = Qs + qbuf * 64 * KPCH;

        // ---- scores: warp tile 16M x 56N (7 n-tiles), K=64 ----
        float acc[7][4];
#pragma unroll
        for (int nt = 0; nt < 7; nt++)
#pragma unroll
            for (int c = 0; c < 4; c++) acc[nt][c] = 0.f;

#pragma unroll
        for (int kk = 0; kk < 8; kk++) {
            int kb = kk * 8;
            uint32_t a[4];
            a[0] = fu(Qb[mrow * KPCH + kb + tig]);
            a[1] = fu(Qb[(mrow + 8) * KPCH + kb + tig]);
            a[2] = fu(Qb[mrow * KPCH + kb + tig + 4]);
            a[3] = fu(Qb[(mrow + 8) * KPCH + kb + tig + 4]);
#pragma unroll
            for (int nt = 0; nt < 7; nt++) {
                int nr = (wn * 56 + nt * 8 + gid) * KPCH;
                uint32_t bb[2] = { fu(Ks[nr + kb + tig]), fu(Ks[nr + kb + tig + 4]) };
                mma8(acc[nt], a, bb);
            }
        }
#pragma unroll
        for (int nt = 0; nt < 7; nt++) {
            int n = wn * 56 + nt * 8 + 2 * tig;
            float2 v0 = { acc[nt][0], acc[nt][1] };
            float2 v1 = { acc[nt][2], acc[nt][3] };
            *(float2*)&Ssm[mrow * SPCH + n]       = v0;
            *(float2*)&Ssm[(mrow + 8) * SPCH + n] = v1;
        }
        __syncthreads();

        // prefetch next q-block while softmax + PV run
        if (qb + 1 < NQB) {
            Q_PREFETCH(qb + 1, qbuf ^ 1);
            CP_COMMIT();
        }

        // ---- masked softmax: warp wid owns rows wid*4 .. wid*4+3 ----
#pragma unroll 1
        for (int rr = 0; rr < 4; rr++) {
            int row = wid * 4 + rr;
            float x[7], mx = -1e30f;
#pragma unroll
            for (int i = 0; i < 7; i++) {
                int j = lane + 32 * i;
                x[i] = (j < LKV) ? Ssm[row * SPCH + j] : -1e30f;
                mx = fmaxf(mx, x[i]);
            }
#pragma unroll
            for (int off = 16; off > 0; off >>= 1)
                mx = fmaxf(mx, __shfl_xor_sync(0xffffffffu, mx, off));
            float e[7], ssum = 0.f;
#pragma unroll
            for (int i = 0; i < 7; i++) {
                int j = lane + 32 * i;
                e[i] = (j < LKV) ? __expf(x[i] - mx) : 0.f;
                ssum += e[i];
            }
#pragma unroll
            for (int off = 16; off > 0; off >>= 1)
                ssum += __shfl_xor_sync(0xffffffffu, ssum, off);
            float inv = 1.f / ssum;
#pragma unroll
            for (int i = 0; i < 7; i++) {
                int j = lane + 32 * i;
                Ssm[row * SPCH + j] = tf32r(e[i] * inv);
            }
        }
        __syncthreads();

        // ---- PV: warp tile 16M x 16N (2 n-tiles), K=224 ----
        float acc2[2][4];
#pragma unroll
        for (int nt = 0; nt < 2; nt++)
#pragma unroll
            for (int c = 0; c < 4; c++) acc2[nt][c] = 0.f;

#pragma unroll 2
        for (int kk = 0; kk < 28; kk++) {
            int kb = kk * 8;
            uint32_t a[4];
            a[0] = fu(Ssm[mrow * SPCH + kb + tig]);
            a[1] = fu(Ssm[(mrow + 8) * SPCH + kb + tig]);
            a[2] = fu(Ssm[mrow * SPCH + kb + tig + 4]);
            a[3] = fu(Ssm[(mrow + 8) * SPCH + kb + tig + 4]);
#pragma unroll
            for (int nt = 0; nt < 2; nt++) {
                int nr = (wn * 16 + nt * 8 + gid) * SPCH;
                uint32_t bb[2] = { fu(VsT[nr + kb + tig]), fu(VsT[nr + kb + tig + 4]) };
                mma8(acc2[nt], a, bb);
            }
        }

        // ---- write ctx ----
        int t0 = qb * 64;
        int t = t0 + mrow;
#pragma unroll
        for (int nt = 0; nt < 2; nt++) {
            int col = h * HDIM + wn * 16 + nt * 8 + 2 * tig;
            if (t < LQ) {
                float2 v = { acc2[nt][0], acc2[nt][1] };
                *(float2*)(out + ((size_t)b * LQ + t) * CDIM + col) = v;
            }
            if (t + 8 < LQ) {
                float2 v = { acc2[nt][2], acc2[nt][3] };
                *(float2*)(out + ((size_t)b * LQ + t + 8) * CDIM + col) = v;
            }
        }
        __syncthreads();   // Ssm reads done before next q-block overwrites
    }
#undef Q_PREFETCH
}

// ---------------- entry point ----------------
extern "C" void kernel_launch(void* const* d_in, const int* in_sizes, int n_in,
                              void* d_out, int out_size) {
    (void)in_sizes; (void)n_in; (void)out_size;
    const float* hs   = (const float*)d_in[0];
    const float* wdwq = (const float*)d_in[3];
    const float* gq   = (const float*)d_in[4];
    const float* beq  = (const float*)d_in[5];
    const float* mq   = (const float*)d_in[6];
    const float* vq   = (const float*)d_in[7];
    const float* Wq   = (const float*)d_in[8];
    const float* bq   = (const float*)d_in[9];
    const float* wdwk = (const float*)d_in[10];
    const float* gk   = (const float*)d_in[11];
    const float* bek  = (const float*)d_in[12];
    const float* mk   = (const float*)d_in[13];
    const float* vk   = (const float*)d_in[14];
    const float* Wk   = (const float*)d_in[15];
    const float* bk   = (const float*)d_in[16];
    const float* wdwv = (const float*)d_in[17];
    const float* gv   = (const float*)d_in[18];
    const float* bev  = (const float*)d_in[19];
    const float* mv   = (const float*)d_in[20];
    const float* vv   = (const float*)d_in[21];
    const float* Wv   = (const float*)d_in[22];
    const float* bv   = (const float*)d_in[23];
    float* out = (float*)d_out;

    cudaFuncSetAttribute(gemm_mma_kernel,
                         cudaFuncAttributeMaxDynamicSharedMemorySize, GEMM_SMEM);
    cudaFuncSetAttribute(attn_mma_kernel,
                         cudaFuncAttributeMaxDynamicSharedMemorySize, ATTN_SMEM);

    cls_copy_kernel<<<BATCH, CDIM>>>(hs);
    conv_q_kernel<<<BATCH * HIN * WIN, CDIM>>>(hs, wdwq, gq, beq, mq, vq);
    conv_kv_kernel<<<BATCH * 196, CDIM>>>(hs, wdwk, gk, bek, mk, vk,
                                          wdwv, gv, bev, mv, vv);
    transpose_w_kernel<<<dim3(12, 12, 3), dim3(32, 8)>>>(Wq, Wk, Wv);
    gemm_mma_kernel<<<dim3(3, MTILES), 256, GEMM_SMEM>>>(bq, bk, bv);
    attn_mma_kernel<<<BATCH * NHEADS, 512, ATTN_SMEM>>>(out);
}

// round 5
// speedup vs baseline: 3.1768x; 1.3466x over previous
#include <cuda_runtime.h>
#include <math.h>
#include <stdint.h>

#define BATCH  64
#define CDIM   384
#define HIN    28
#define WIN    28
#define LQ     785
#define LKV    197
#define NHEADS 6
#define HDIM   64
#define EPSB   1e-5f
#define QSCALE 0.051031036307982884f

#define MQP   50304            // 393 * 128
#define MKVP  12672            // 99 * 128
#define QTILES  393
#define KVTILES 99
#define MTILES  (QTILES + 2 * KVTILES)   // 591

// ---------------- device scratch ----------------
__device__ float g_qc[MQP  * CDIM];
__device__ float g_kc[MKVP * CDIM];
__device__ float g_vc[MKVP * CDIM];
__device__ float g_Q [MQP  * CDIM];
__device__ float g_K [MKVP * CDIM];
__device__ float g_V [MKVP * CDIM];
__device__ float g_WT[3 * CDIM * CDIM];   // W transposed: [n][k], tf32-rounded

// ---------------- helpers ----------------
__device__ __forceinline__ float tf32r(float x) {
    uint32_t u;
    asm("cvt.rna.tf32.f32 %0, %1;" : "=r"(u) : "f"(x));
    return __uint_as_float(u);
}
__device__ __forceinline__ uint32_t fu(float x) { return __float_as_uint(x); }
__device__ __forceinline__ uint32_t smem_u32(const void* p) {
    uint32_t a;
    asm("{ .reg .u64 t; cvta.to.shared.u64 t, %1; cvt.u32.u64 %0, t; }" : "=r"(a) : "l"(p));
    return a;
}
__device__ __forceinline__ void cp16(uint32_t s, const void* g) {
    asm volatile("cp.async.cg.shared.global [%0], [%1], 16;" :: "r"(s), "l"(g) : "memory");
}
#define CP_COMMIT() asm volatile("cp.async.commit_group;" ::: "memory")
template <int N>
__device__ __forceinline__ void cp_wait() {
    asm volatile("cp.async.wait_group %0;" :: "n"(N) : "memory");
}

// D += A(16x8,row) * B(8x8,col)   tf32
__device__ __forceinline__ void mma8(float* d, const uint32_t* a, const uint32_t* b) {
    asm volatile(
        "mma.sync.aligned.m16n8k8.row.col.f32.tf32.tf32.f32 "
        "{%0,%1,%2,%3}, {%4,%5,%6,%7}, {%8,%9}, {%0,%1,%2,%3};"
        : "+f"(d[0]), "+f"(d[1]), "+f"(d[2]), "+f"(d[3])
        : "r"(a[0]), "r"(a[1]), "r"(a[2]), "r"(a[3]), "r"(b[0]), "r"(b[1]));
}

// ---------------- cls token copy (tf32-rounded) ----------------
__global__ void cls_copy_kernel(const float* __restrict__ hs) {
    int b = blockIdx.x, c = threadIdx.x;
    float v = tf32r(hs[(size_t)b * LQ * CDIM + c]);
    g_qc[(size_t)b * LQ  * CDIM + c] = v;
    g_kc[(size_t)b * LKV * CDIM + c] = v;
    g_vc[(size_t)b * LKV * CDIM + c] = v;
}

// ---------------- depthwise 3x3 s1 conv + BN (q), one CTA per output row ----------------
__global__ __launch_bounds__(CDIM) void conv_q_row_kernel(
    const float* __restrict__ hs, const float* __restrict__ wdw,
    const float* __restrict__ gam, const float* __restrict__ bet,
    const float* __restrict__ mean, const float* __restrict__ var) {
    int c  = threadIdx.x;
    int oh = blockIdx.x % HIN;
    int b  = blockIdx.x / HIN;
    const float* xb = hs + (size_t)b * LQ * CDIM + CDIM;

    float w[9];
#pragma unroll
    for (int j = 0; j < 9; j++) w[j] = wdw[j * CDIM + c];
    float s  = gam[c] * rsqrtf(var[c] + EPSB);
    float sh = bet[c] - mean[c] * s;

    bool topv = oh > 0, botv = oh < HIN - 1;
    const float* r0 = xb + (size_t)(oh - 1) * WIN * CDIM + c;
    const float* r1 = xb + (size_t)oh       * WIN * CDIM + c;
    const float* r2 = xb + (size_t)(oh + 1) * WIN * CDIM + c;
    float* orow = g_qc + (size_t)b * LQ * CDIM + (size_t)(1 + oh * WIN) * CDIM + c;

    float a0p = 0.f, a1p = 0.f, a2p = 0.f;
    float a0c = topv ? r0[0] : 0.f;
    float a1c = r1[0];
    float a2c = botv ? r2[0] : 0.f;

#pragma unroll
    for (int ow = 0; ow < WIN; ow++) {
        float a0n = 0.f, a1n = 0.f, a2n = 0.f;
        if (ow < WIN - 1) {
            size_t o = (size_t)(ow + 1) * CDIM;
            a0n = topv ? r0[o] : 0.f;
            a1n = r1[o];
            a2n = botv ? r2[o] : 0.f;
        }
        float acc = a0p * w[0];
        acc = fmaf(a0c, w[1], acc); acc = fmaf(a0n, w[2], acc);
        acc = fmaf(a1p, w[3], acc); acc = fmaf(a1c, w[4], acc);
        acc = fmaf(a1n, w[5], acc); acc = fmaf(a2p, w[6], acc);
        acc = fmaf(a2c, w[7], acc); acc = fmaf(a2n, w[8], acc);
        orow[(size_t)ow * CDIM] = tf32r(acc * s + sh);
        a0p = a0c; a0c = a0n;
        a1p = a1c; a1c = a1n;
        a2p = a2c; a2c = a2n;
    }
}

// ---------------- depthwise 3x3 s2 conv + BN (k,v), one CTA per output row ----------------
__global__ __launch_bounds__(CDIM) void conv_kv_row_kernel(
    const float* __restrict__ hs,
    const float* __restrict__ wk, const float* __restrict__ gk,
    const float* __restrict__ bek, const float* __restrict__ mk,
    const float* __restrict__ vk,
    const float* __restrict__ wv, const float* __restrict__ gv,
    const float* __restrict__ bev, const float* __restrict__ mv,
    const float* __restrict__ vvv) {
    int c  = threadIdx.x;
    int oh = blockIdx.x % 14;
    int b  = blockIdx.x / 14;
    const float* xb = hs + (size_t)b * LQ * CDIM + CDIM;

    float fk[9], fv[9];
#pragma unroll
    for (int j = 0; j < 9; j++) {
        fk[j] = wk[j * CDIM + c];
        fv[j] = wv[j * CDIM + c];
    }
    float sk  = gk[c] * rsqrtf(vk[c]  + EPSB);
    float shk = bek[c] - mk[c] * sk;
    float sv  = gv[c] * rsqrtf(vvv[c] + EPSB);
    float shv = bev[c] - mv[c] * sv;

    bool topv = oh > 0;                   // input row 2*oh-1
    const float* r0 = xb + (size_t)(2 * oh - 1) * WIN * CDIM + c;
    const float* r1 = xb + (size_t)(2 * oh)     * WIN * CDIM + c;
    const float* r2 = xb + (size_t)(2 * oh + 1) * WIN * CDIM + c;

    size_t obase = (size_t)b * LKV * CDIM + (size_t)(1 + oh * 14) * CDIM + c;
    float* ok = g_kc + obase;
    float* ov = g_vc + obase;

    // window cols 2j-1, 2j, 2j+1
    float a0m = 0.f, a1m = 0.f, a2m = 0.f;
    float a0c = topv ? r0[0] : 0.f, a1c = r1[0], a2c = r2[0];
    float a0p = topv ? r0[CDIM] : 0.f, a1p = r1[CDIM], a2p = r2[CDIM];

#pragma unroll
    for (int j = 0; j < 14; j++) {
        float ak = a0m * fk[0];
        ak = fmaf(a0c, fk[1], ak); ak = fmaf(a0p, fk[2], ak);
        ak = fmaf(a1m, fk[3], ak); ak = fmaf(a1c, fk[4], ak);
        ak = fmaf(a1p, fk[5], ak); ak = fmaf(a2m, fk[6], ak);
        ak = fmaf(a2c, fk[7], ak); ak = fmaf(a2p, fk[8], ak);
        float av = a0m * fv[0];
        av = fmaf(a0c, fv[1], av); av = fmaf(a0p, fv[2], av);
        av = fmaf(a1m, fv[3], av); av = fmaf(a1c, fv[4], av);
        av = fmaf(a1p, fv[5], av); av = fmaf(a2m, fv[6], av);
        av = fmaf(a2c, fv[7], av); av = fmaf(a2p, fv[8], av);
        ok[(size_t)j * CDIM] = tf32r(ak * sk + shk);
        ov[(size_t)j * CDIM] = tf32r(av * sv + shv);
        if (j < 13) {
            size_t o2 = (size_t)(2 * j + 2) * CDIM;
            size_t o3 = (size_t)(2 * j + 3) * CDIM;
            a0m = a0p; a1m = a1p; a2m = a2p;
            a0c = topv ? r0[o2] : 0.f; a1c = r1[o2]; a2c = r2[o2];
            a0p = topv ? r0[o3] : 0.f; a1p = r1[o3]; a2p = r2[o3];
        }
    }
}

// ---------------- W transpose (tf32-rounded): g_WT[n][k] = W[k][n] ----------------
__global__ void transpose_w_kernel(const float* __restrict__ Wq,
                                   const float* __restrict__ Wk,
                                   const float* __restrict__ Wv) {
    __shared__ float t[32][33];
    int z = blockIdx.z;
    const float* src = (z == 0) ? Wq : (z == 1) ? Wk : Wv;
    float* dst = g_WT + (size_t)z * CDIM * CDIM;
    int tx = threadIdx.x, ty = threadIdx.y;
    int x = blockIdx.x * 32 + tx;
    int y0 = blockIdx.y * 32;
#pragma unroll
    for (int r = 0; r < 32; r += 8)
        t[ty + r][tx] = src[(size_t)(y0 + ty + r) * CDIM + x];
    __syncthreads();
    int n = blockIdx.x * 32 + ty;
#pragma unroll
    for (int r = 0; r < 32; r += 8)
        dst[(size_t)(n + r) * CDIM + y0 + tx] = tf32r(t[tx][ty + r]);
}

// ---------------- tf32 mma GEMM, 3-stage cp.async pipeline (unchanged) ----------------
#define GPITCH  36
#define GSTAGEF (2 * 128 * GPITCH)
#define GEMM_SMEM (3 * GSTAGEF * 4)

__global__ __launch_bounds__(256, 2) void gemm_mma_kernel(
    const float* __restrict__ bq, const float* __restrict__ bk,
    const float* __restrict__ bv) {
    extern __shared__ float gsm[];

    int mt = blockIdx.y, ntile = blockIdx.x;
    int sel, mloc;
    if (mt < QTILES)                 { sel = 0; mloc = mt; }
    else if (mt < QTILES + KVTILES)  { sel = 1; mloc = mt - QTILES; }
    else                             { sel = 2; mloc = mt - QTILES - KVTILES; }
    const float* A    = (sel == 0) ? g_qc : (sel == 1) ? g_kc : g_vc;
    float*       C    = (sel == 0) ? g_Q  : (sel == 1) ? g_K  : g_V;
    const float* WT   = g_WT + (size_t)sel * CDIM * CDIM;
    const float* bias = (sel == 0) ? bq : (sel == 1) ? bk : bv;
    const float oscale = (sel == 0) ? QSCALE : 1.0f;
    const int m0 = mloc * 128, n0 = ntile * 128;

    const int tid = threadIdx.x, lane = tid & 31, wid = tid >> 5;
    const int gid = lane >> 2, tig = lane & 3;
    const int wm = wid & 3, wn = wid >> 2;

    const int lr = tid >> 3;
    const int lc = (tid & 7) << 2;
    const float* Ag = A  + ((size_t)(m0 + lr)) * CDIM + lc;
    const float* Bg = WT + ((size_t)(n0 + lr)) * CDIM + lc;
    uint32_t sbase = smem_u32(gsm);

    float acc[2][8][4];
#pragma unroll
    for (int i = 0; i < 2; i++)
#pragma unroll
        for (int j = 0; j < 8; j++)
#pragma unroll
            for (int c = 0; c < 4; c++) acc[i][j][c] = 0.f;

#define G_ISSUE(s)                                                              \
    do {                                                                        \
        int st_ = (s) % 3;                                                      \
        int k0_ = (s) * 32;                                                     \
        uint32_t as_ = sbase + (uint32_t)(st_ * GSTAGEF) * 4u;                  \
        uint32_t bs_ = as_ + (uint32_t)(128 * GPITCH) * 4u;                     \
        _Pragma("unroll")                                                       \
        for (int i_ = 0; i_ < 4; i_++) {                                        \
            cp16(as_ + (uint32_t)(((lr + 32 * i_) * GPITCH + lc) * 4),          \
                 Ag + (size_t)(32 * i_) * CDIM + k0_);                          \
            cp16(bs_ + (uint32_t)(((lr + 32 * i_) * GPITCH + lc) * 4),          \
                 Bg + (size_t)(32 * i_) * CDIM + k0_);                          \
        }                                                                       \
    } while (0)

    G_ISSUE(0); CP_COMMIT();
    G_ISSUE(1); CP_COMMIT();

#pragma unroll 1
    for (int s = 0; s < 12; s++) {
        if (s <= 9)       { G_ISSUE(s + 2); CP_COMMIT(); cp_wait<2>(); }
        else if (s == 10) cp_wait<1>();
        else              cp_wait<0>();
        __syncthreads();

        const float* Ab = gsm + (s % 3) * GSTAGEF;
        const float* Bb = Ab + 128 * GPITCH;
#pragma unroll
        for (int kk = 0; kk < 4; kk++) {
            int kb = kk * 8;
            uint32_t a[2][4];
#pragma unroll
            for (int m2 = 0; m2 < 2; m2++) {
                int mr = (wm * 32 + m2 * 16 + gid) * GPITCH;
                a[m2][0] = fu(Ab[mr + kb + tig]);
                a[m2][1] = fu(Ab[mr + 8 * GPITCH + kb + tig]);
                a[m2][2] = fu(Ab[mr + kb + tig + 4]);
                a[m2][3] = fu(Ab[mr + 8 * GPITCH + kb + tig + 4]);
            }
#pragma unroll
            for (int nt = 0; nt < 8; nt++) {
                int nr = (wn * 64 + nt * 8 + gid) * GPITCH;
                uint32_t bb[2] = { fu(Bb[nr + kb + tig]), fu(Bb[nr + kb + tig + 4]) };
                mma8(acc[0][nt], a[0], bb);
                mma8(acc[1][nt], a[1], bb);
            }
        }
        __syncthreads();
    }
#undef G_ISSUE

#pragma unroll
    for (int m2 = 0; m2 < 2; m2++) {
        int row = m0 + wm * 32 + m2 * 16 + gid;
#pragma unroll
        for (int nt = 0; nt < 8; nt++) {
            int col = n0 + wn * 64 + nt * 8 + 2 * tig;
            float b0 = bias[col], b1 = bias[col + 1];
            float2 v0, v1;
            v0.x = tf32r((acc[m2][nt][0] + b0) * oscale);
            v0.y = tf32r((acc[m2][nt][1] + b1) * oscale);
            v1.x = tf32r((acc[m2][nt][2] + b0) * oscale);
            v1.y = tf32r((acc[m2][nt][3] + b1) * oscale);
            *(float2*)(C + (size_t)row * CDIM + col)       = v0;
            *(float2*)(C + (size_t)(row + 8) * CDIM + col) = v1;
        }
    }
}

// ---------------- warp-autonomous attention: registers all the way ----------------
#define NKV2  200                 // 25 * 8 live kv columns
#define KP2   68                  // Ks pitch
#define VP2   204                 // VsT pitch
#define NTIL  50                  // ceil(785/16)
#define NWARP 8
#define ATTN_SMEM ((NKV2 * KP2 + 64 * VP2) * 4)   // 106,624 B

__global__ __launch_bounds__(256, 1) void attn_mma_kernel(float* __restrict__ out) {
    extern __shared__ float sm[];
    float* Ks  = sm;                 // [200][68]  K rows (kv), k contiguous
    float* VsT = sm + NKV2 * KP2;    // [64][204]  V^T: rows=dim, cols=kv

    int bh = blockIdx.x;
    int b = bh / NHEADS, h = bh % NHEADS;
    int tid = threadIdx.x, lane = tid & 31, wid = tid >> 5;
    int gid = lane >> 2, tig = lane & 3;

    const float* Kg = g_K + ((size_t)b * LKV) * CDIM + h * HDIM;
    const float* Vg = g_V + ((size_t)b * LKV) * CDIM + h * HDIM;
    const float* Qg = g_Q + ((size_t)b * LQ)  * CDIM + h * HDIM;

    // load K (rows >=197 zero) and V transposed (kv cols >=197 zero)
    for (int i = tid; i < NKV2 * 16; i += 256) {
        int n = i >> 4, k4 = (i & 15) << 2;
        float4 kv = make_float4(0.f, 0.f, 0.f, 0.f), vv = kv;
        if (n < LKV) {
            kv = *(const float4*)(Kg + (size_t)n * CDIM + k4);
            vv = *(const float4*)(Vg + (size_t)n * CDIM + k4);
        }
        *(float4*)&Ks[n * KP2 + k4] = kv;
        VsT[(k4 + 0) * VP2 + n] = vv.x;
        VsT[(k4 + 1) * VP2 + n] = vv.y;
        VsT[(k4 + 2) * VP2 + n] = vv.z;
        VsT[(k4 + 3) * VP2 + n] = vv.w;
    }
    __syncthreads();

    const int src0 = (lane & ~3) | (tig >> 1);
    const int src1 = src0 + 2;
    const bool odd = (tig & 1) != 0;

#pragma unroll 1
    for (int it = wid; it < NTIL; it += NWARP) {
        const int t0 = it * 16;
        const int tA = t0 + gid, tB = tA + 8;
        const bool vA = tA < LQ, vB = tB < LQ;
        const float* qrA = Qg + (size_t)tA * CDIM;
        const float* qrB = Qg + (size_t)tB * CDIM;

        // Q a-fragments straight from gmem (read-once)
        uint32_t qa[8][4];
#pragma unroll
        for (int kk = 0; kk < 8; kk++) {
            int kb = kk * 8 + tig;
            qa[kk][0] = vA ? fu(qrA[kb])     : 0u;
            qa[kk][1] = vB ? fu(qrB[kb])     : 0u;
            qa[kk][2] = vA ? fu(qrA[kb + 4]) : 0u;
            qa[kk][3] = vB ? fu(qrB[kb + 4]) : 0u;
        }

        // ---- scores: 16 x 200, K=64 (25 n-tiles, all in registers) ----
        float sc[25][4];
#pragma unroll
        for (int nt = 0; nt < 25; nt++)
#pragma unroll
            for (int c = 0; c < 4; c++) sc[nt][c] = 0.f;

#pragma unroll
        for (int kk = 0; kk < 8; kk++) {
            int kb = kk * 8 + tig;
#pragma unroll
            for (int nt = 0; nt < 25; nt++) {
                int nr = (nt * 8 + gid) * KP2;
                uint32_t bb[2] = { fu(Ks[nr + kb]), fu(Ks[nr + kb + 4]) };
                mma8(sc[nt], qa[kk], bb);
            }
        }

        // ---- warp-local masked softmax (rows tA, tB) ----
        float mx0 = -1e30f, mx1 = -1e30f;
#pragma unroll
        for (int nt = 0; nt < 25; nt++) {
            int j = nt * 8 + 2 * tig;
            if (j < LKV)     { mx0 = fmaxf(mx0, sc[nt][0]); mx1 = fmaxf(mx1, sc[nt][2]); }
            if (j + 1 < LKV) { mx0 = fmaxf(mx0, sc[nt][1]); mx1 = fmaxf(mx1, sc[nt][3]); }
        }
        mx0 = fmaxf(mx0, __shfl_xor_sync(0xffffffffu, mx0, 1));
        mx0 = fmaxf(mx0, __shfl_xor_sync(0xffffffffu, mx0, 2));
        mx1 = fmaxf(mx1, __shfl_xor_sync(0xffffffffu, mx1, 1));
        mx1 = fmaxf(mx1, __shfl_xor_sync(0xffffffffu, mx1, 2));

        float l0 = 0.f, l1 = 0.f;
#pragma unroll
        for (int nt = 0; nt < 25; nt++) {
            int j = nt * 8 + 2 * tig;
            float e0 = (j < LKV)     ? __expf(sc[nt][0] - mx0) : 0.f;
            float e1 = (j + 1 < LKV) ? __expf(sc[nt][1] - mx0) : 0.f;
            float e2 = (j < LKV)     ? __expf(sc[nt][2] - mx1) : 0.f;
            float e3 = (j + 1 < LKV) ? __expf(sc[nt][3] - mx1) : 0.f;
            sc[nt][0] = e0; sc[nt][1] = e1; sc[nt][2] = e2; sc[nt][3] = e3;
            l0 += e0 + e1;
            l1 += e2 + e3;
        }
        l0 += __shfl_xor_sync(0xffffffffu, l0, 1);
        l0 += __shfl_xor_sync(0xffffffffu, l0, 2);
        l1 += __shfl_xor_sync(0xffffffffu, l1, 1);
        l1 += __shfl_xor_sync(0xffffffffu, l1, 2);
        float inv0 = 1.f / l0, inv1 = 1.f / l1;

        // ---- PV: repack probs c-layout -> a-frag via shuffles, mma against V^T ----
        float acc2[8][4];
#pragma unroll
        for (int nt = 0; nt < 8; nt++)
#pragma unroll
            for (int c = 0; c < 4; c++) acc2[nt][c] = 0.f;

#pragma unroll
        for (int kk = 0; kk < 25; kk++) {
            float v0 = sc[kk][0], v1 = sc[kk][1], v2 = sc[kk][2], v3 = sc[kk][3];
            float t00 = __shfl_sync(0xffffffffu, v0, src0);
            float t01 = __shfl_sync(0xffffffffu, v1, src0);
            float t10 = __shfl_sync(0xffffffffu, v2, src0);
            float t11 = __shfl_sync(0xffffffffu, v3, src0);
            float u00 = __shfl_sync(0xffffffffu, v0, src1);
            float u01 = __shfl_sync(0xffffffffu, v1, src1);
            float u10 = __shfl_sync(0xffffffffu, v2, src1);
            float u11 = __shfl_sync(0xffffffffu, v3, src1);
            uint32_t a[4];
            a[0] = fu(tf32r((odd ? t01 : t00) * inv0));
            a[1] = fu(tf32r((odd ? t11 : t10) * inv1));
            a[2] = fu(tf32r((odd ? u01 : u00) * inv0));
            a[3] = fu(tf32r((odd ? u11 : u10) * inv1));
            int kb = kk * 8 + tig;
#pragma unroll
            for (int nt = 0; nt < 8; nt++) {
                int nr = (nt * 8 + gid) * VP2;
                uint32_t bb[2] = { fu(VsT[nr + kb]), fu(VsT[nr + kb + 4]) };
                mma8(acc2[nt], a, bb);
            }
        }

        // ---- write ctx ----
#pragma unroll
        for (int nt = 0; nt < 8; nt++) {
            int col = h * HDIM + nt * 8 + 2 * tig;
            if (vA) {
                float2 v = { acc2[nt][0], acc2[nt][1] };
                *(float2*)(out + ((size_t)b * LQ + tA) * CDIM + col) = v;
            }
            if (vB) {
                float2 v = { acc2[nt][2], acc2[nt][3] };
                *(float2*)(out + ((size_t)b * LQ + tB) * CDIM + col) = v;
            }
        }
    }
}

// ---------------- entry point ----------------
extern "C" void kernel_launch(void* const* d_in, const int* in_sizes, int n_in,
                              void* d_out, int out_size) {
    (void)in_sizes; (void)n_in; (void)out_size;
    const float* hs   = (const float*)d_in[0];
    const float* wdwq = (const float*)d_in[3];
    const float* gq   = (const float*)d_in[4];
    const float* beq  = (const float*)d_in[5];
    const float* mq   = (const float*)d_in[6];
    const float* vq   = (const float*)d_in[7];
    const float* Wq   = (const float*)d_in[8];
    const float* bq   = (const float*)d_in[9];
    const float* wdwk = (const float*)d_in[10];
    const float* gk   = (const float*)d_in[11];
    const float* bek  = (const float*)d_in[12];
    const float* mk   = (const float*)d_in[13];
    const float* vk   = (const float*)d_in[14];
    const float* Wk   = (const float*)d_in[15];
    const float* bk   = (const float*)d_in[16];
    const float* wdwv = (const float*)d_in[17];
    const float* gv   = (const float*)d_in[18];
    const float* bev  = (const float*)d_in[19];
    const float* mv   = (const float*)d_in[20];
    const float* vv   = (const float*)d_in[21];
    const float* Wv   = (const float*)d_in[22];
    const float* bv   = (const float*)d_in[23];
    float* out = (float*)d_out;

    cudaFuncSetAttribute(gemm_mma_kernel,
                         cudaFuncAttributeMaxDynamicSharedMemorySize, GEMM_SMEM);
    cudaFuncSetAttribute(attn_mma_kernel,
                         cudaFuncAttributeMaxDynamicSharedMemorySize, ATTN_SMEM);

    cls_copy_kernel<<<BATCH, CDIM>>>(hs);
    conv_q_row_kernel<<<BATCH * HIN, CDIM>>>(hs, wdwq, gq, beq, mq, vq);
    conv_kv_row_kernel<<<BATCH * 14, CDIM>>>(hs, wdwk, gk, bek, mk, vk,
                                             wdwv, gv, bev, mv, vv);
    transpose_w_kernel<<<dim3(12, 12, 3), dim3(32, 8)>>>(Wq, Wk, Wv);
    gemm_mma_kernel<<<dim3(3, MTILES), 256, GEMM_SMEM>>>(bq, bk, bv);
    attn_mma_kernel<<<BATCH * NHEADS, 256, ATTN_SMEM>>>(out);
}